// round 8
// baseline (speedup 1.0000x reference)
#include <cuda_runtime.h>
#include <cuda_fp16.h>
#include <math.h>
#include <stdint.h>

#define B_  4
#define T_  2048
#define C_  2048
#define NH  16
#define NKV 4
#define HD  128
#define KVW 1024
#define M_  (B_ * T_)   // 8192

// ---------------- scratch (no allocations allowed) ----------------
__device__ float g_q[(size_t)M_ * C_];          // x@Wq fp32
__device__ float g_kv[(size_t)M_ * KVW];        // x@Wkv fp32
__device__ __half g_xh[(size_t)M_ * C_];        // x fp16
__device__ __half g_qh[(size_t)M_ * C_];        // l2norm(q)*scale
__device__ __half g_kh[(size_t)M_ * 512];       // l2norm(k)
__device__ __half g_vh[(size_t)M_ * 512];       // v fp16
__device__ __half g_yh[(size_t)M_ * C_];        // attn out fp16
__device__ __half g_wqt[(size_t)C_ * C_];       // WqT  [N][K]
__device__ __half g_wkvt[(size_t)KVW * C_];     // WkvT [N][K]
__device__ __half g_wpt[(size_t)C_ * C_];       // WprojT [N][K]

// ================= helpers =================
__device__ __forceinline__ uint32_t smem_to_u32(const void* p) {
    uint32_t a;
    asm("{ .reg .u64 t; cvta.to.shared.u64 t, %1; cvt.u32.u64 %0, t; }"
        : "=r"(a) : "l"(p));
    return a;
}
#define SWZ(off) ((off) ^ (((off) >> 3) & 0x70))

__device__ __forceinline__ void ldm4(uint32_t* r, uint32_t addr) {
    asm volatile("ldmatrix.sync.aligned.m8n8.x4.shared.b16 {%0,%1,%2,%3}, [%4];"
        : "=r"(r[0]), "=r"(r[1]), "=r"(r[2]), "=r"(r[3]) : "r"(addr));
}
__device__ __forceinline__ void ldm2(uint32_t* r, uint32_t addr) {
    asm volatile("ldmatrix.sync.aligned.m8n8.x2.shared.b16 {%0,%1}, [%2];"
        : "=r"(r[0]), "=r"(r[1]) : "r"(addr));
}
__device__ __forceinline__ void ldm4t(uint32_t* r, uint32_t addr) {
    asm volatile("ldmatrix.sync.aligned.m8n8.x4.trans.shared.b16 {%0,%1,%2,%3}, [%4];"
        : "=r"(r[0]), "=r"(r[1]), "=r"(r[2]), "=r"(r[3]) : "r"(addr));
}
__device__ __forceinline__ void mma_f16(float* c, const uint32_t* a, const uint32_t* b) {
    asm volatile("mma.sync.aligned.m16n8k16.row.col.f32.f16.f16.f32 "
        "{%0,%1,%2,%3}, {%4,%5,%6,%7}, {%8,%9}, {%0,%1,%2,%3};"
        : "+f"(c[0]), "+f"(c[1]), "+f"(c[2]), "+f"(c[3])
        : "r"(a[0]), "r"(a[1]), "r"(a[2]), "r"(a[3]), "r"(b[0]), "r"(b[1]));
}
__device__ __forceinline__ void cp16(uint32_t dst, const void* src) {
    asm volatile("cp.async.cg.shared.global [%0], [%1], 16;" :: "r"(dst), "l"(src));
}
#define CP_COMMIT() asm volatile("cp.async.commit_group;" ::: "memory")
#define CP_WAIT0()  asm volatile("cp.async.wait_group 0;" ::: "memory")
#define CP_WAIT1()  asm volatile("cp.async.wait_group 1;" ::: "memory")
#define CP_WAIT2()  asm volatile("cp.async.wait_group 2;" ::: "memory")

__device__ __forceinline__ uint32_t pack_h2(float x, float y) {
    __half2 t = __float22half2_rn(make_float2(x, y));
    return *(uint32_t*)&t;
}

// ================= staging kernels =================
__global__ void __launch_bounds__(512) convert_h(const float4* __restrict__ x,
                                                 uint2* __restrict__ hi, int n4)
{
    for (int i = blockIdx.x * 512 + threadIdx.x; i < n4; i += gridDim.x * 512) {
        float4 v = x[i];
        hi[i] = make_uint2(pack_h2(v.x, v.y), pack_h2(v.z, v.w));
    }
}

// W [K][N] fp32 -> WT [N][K] fp16
__global__ void __launch_bounds__(256) transpose_h(const float* __restrict__ W,
                                                   __half* __restrict__ Tt, int K, int N)
{
    __shared__ float t[32][33];
    int n0 = blockIdx.x * 32, k0 = blockIdx.y * 32;
    int tx = threadIdx.x, ty = threadIdx.y;
#pragma unroll
    for (int j = 0; j < 4; j++)
        t[ty + 8 * j][tx] = W[(size_t)(k0 + ty + 8 * j) * N + n0 + tx];
    __syncthreads();
#pragma unroll
    for (int j = 0; j < 4; j++)
        Tt[(size_t)(n0 + ty + 8 * j) * K + k0 + tx] = __float2half_rn(t[tx][ty + 8 * j]);
}

// ================= HMMA fp16 GEMM, 3-stage pipeline =================
// C = A * B^T.  A [M][K] fp16, B [N][K] fp16.  128x128 tile, BK=64, 256 thr.
// stage = 32KB (A 16KB + B 16KB), 3 stages, ONE syncthreads per k-chunk.
__device__ __forceinline__ void cp_panel(uint32_t dstBase, const __half* __restrict__ src,
                                         int ldk, int row0, int k0)
{
    int tid = threadIdx.x;
#pragma unroll
    for (int i = 0; i < 4; i++) {
        int l = tid + 256 * i;
        int r = l >> 3, ch = l & 7;
        cp16(dstBase + SWZ(r * 128 + ch * 16), src + (size_t)(row0 + r) * ldk + k0 + ch * 8);
    }
}

__global__ void __launch_bounds__(256) gemm_mma(const __half* __restrict__ Ah,
                                                const __half* __restrict__ Bt,
                                                float* __restrict__ Cc, int K, int N)
{
    extern __shared__ char sm[];
    uint32_t sb = smem_to_u32(sm);
    const int tid = threadIdx.x, wid = tid >> 5, lane = tid & 31;
    const int row0 = blockIdx.y * 128, col0 = blockIdx.x * 128;
    const int wm = (wid >> 2) * 64;
    const int wn = (wid & 3) * 32;

    float acc[4][4][4];
#pragma unroll
    for (int a = 0; a < 4; a++)
#pragma unroll
        for (int b = 0; b < 4; b++)
#pragma unroll
            for (int c = 0; c < 4; c++) acc[a][b][c] = 0.f;

    const int KIT = K >> 6;
    // prologue: chunks 0,1 into stages 0,1
#pragma unroll
    for (int p = 0; p < 2; p++) {
        uint32_t st = sb + p * 32768;
        cp_panel(st,         Ah, K, row0, p * 64);
        cp_panel(st + 16384, Bt, K, col0, p * 64);
        CP_COMMIT();
    }

    int stage = 0;
    for (int kc = 0; kc < KIT; kc++) {
        if (kc + 1 < KIT) CP_WAIT1(); else CP_WAIT0();
        __syncthreads();
        if (kc + 2 < KIT) {
            int ps = stage + 2; if (ps >= 3) ps -= 3;
            uint32_t st2 = sb + ps * 32768;
            int k0 = (kc + 2) * 64;
            cp_panel(st2,         Ah, K, row0, k0);
            cp_panel(st2 + 16384, Bt, K, col0, k0);
            CP_COMMIT();
        }

        uint32_t st = sb + stage * 32768;
#pragma unroll
        for (int ks = 0; ks < 4; ks++) {
            uint32_t af[4][4], bf[4][2];
            const int arow = wm + (lane & 15);
            const int acol = ks * 32 + ((lane >> 4) & 1) * 16;
#pragma unroll
            for (int mt = 0; mt < 4; mt++)
                ldm4(af[mt], st + SWZ((uint32_t)(arow + mt * 16) * 128 + acol));
            const int brow = wn + (lane & 7);
            const int bcol = ks * 32 + ((lane >> 3) & 1) * 16;
#pragma unroll
            for (int nt = 0; nt < 4; nt++)
                ldm2(bf[nt], st + 16384 + SWZ((uint32_t)(brow + nt * 8) * 128 + bcol));
#pragma unroll
            for (int mt = 0; mt < 4; mt++)
#pragma unroll
                for (int nt = 0; nt < 4; nt++)
                    mma_f16(acc[mt][nt], af[mt], bf[nt]);
        }
        if (++stage == 3) stage = 0;
    }

    const int r0 = row0 + wm + (lane >> 2);
    const int c0 = col0 + wn + (lane & 3) * 2;
#pragma unroll
    for (int mt = 0; mt < 4; mt++)
#pragma unroll
        for (int nt = 0; nt < 4; nt++) {
            *(float2*)(Cc + (size_t)(r0 + mt * 16) * N + c0 + nt * 8) =
                make_float2(acc[mt][nt][0], acc[mt][nt][1]);
            *(float2*)(Cc + (size_t)(r0 + mt * 16 + 8) * N + c0 + nt * 8) =
                make_float2(acc[mt][nt][2], acc[mt][nt][3]);
        }
}

// ================= prepass: l2norm q -> fp16 (pre-scaled) =================
__global__ void __launch_bounds__(256) qnorm_h()
{
    const size_t row = blockIdx.x;
    const float4* p = (const float4*)(g_q + row * C_);
    float ss = 0.f;
    for (int i = threadIdx.x; i < C_ / 4; i += 256) {
        float4 v = p[i];
        ss += v.x * v.x + v.y * v.y + v.z * v.z + v.w * v.w;
    }
#pragma unroll
    for (int off = 16; off; off >>= 1) ss += __shfl_xor_sync(0xffffffffu, ss, off);
    __shared__ float red[8];
    if ((threadIdx.x & 31) == 0) red[threadIdx.x >> 5] = ss;
    __syncthreads();
    float tot = red[0] + red[1] + red[2] + red[3] + red[4] + red[5] + red[6] + red[7];
    float sc = 0.08838834764831845f / (sqrtf(tot) + 1e-12f);
    uint2* dst = (uint2*)(g_qh + row * C_);
    for (int i = threadIdx.x; i < C_ / 4; i += 256) {
        float4 v = p[i];
        dst[i] = make_uint2(pack_h2(v.x * sc, v.y * sc), pack_h2(v.z * sc, v.w * sc));
    }
}

// ================= prepass: l2norm k + v -> fp16 =================
__global__ void __launch_bounds__(128) kvnorm_h()
{
    const size_t row = blockIdx.x;
    const float4* kv = (const float4*)(g_kv + row * KVW);
    float4 kvv = kv[threadIdx.x];
    float ss = kvv.x * kvv.x + kvv.y * kvv.y + kvv.z * kvv.z + kvv.w * kvv.w;
#pragma unroll
    for (int off = 16; off; off >>= 1) ss += __shfl_xor_sync(0xffffffffu, ss, off);
    __shared__ float red[4];
    if ((threadIdx.x & 31) == 0) red[threadIdx.x >> 5] = ss;
    __syncthreads();
    float inv = 1.f / (sqrtf(red[0] + red[1] + red[2] + red[3]) + 1e-12f);

    ((uint2*)(g_kh + row * 512))[threadIdx.x] =
        make_uint2(pack_h2(kvv.x * inv, kvv.y * inv), pack_h2(kvv.z * inv, kvv.w * inv));

    float4 vv = kv[128 + threadIdx.x];
    ((uint2*)(g_vh + row * 512))[threadIdx.x] =
        make_uint2(pack_h2(vv.x, vv.y), pack_h2(vv.z, vv.w));
}

// ================= HMMA flash attention =================
// Scores are bounded: |s| <= 1/sqrt(HD) (q,k unit-normalized, q pre-scaled),
// so softmax uses fixed max m=0 -> no online max, no O rescale.
// BQ=BKV=64, 128 threads. smem: Q 16KB + 3 stages x (K 16KB + V 16KB) = 112KB.
__device__ __forceinline__ void load_tile64(uint32_t dstBase, const __half* __restrict__ src,
                                            size_t stride)
{
    int tid = threadIdx.x;
#pragma unroll
    for (int i = 0; i < 8; i++) {
        int lin = tid + 128 * i;
        int r = lin >> 4, ch = lin & 15;
        cp16(dstBase + (ch >> 3) * 8192 + SWZ(r * 128 + (ch & 7) * 16),
             src + (size_t)r * stride + ch * 8);
    }
}

__global__ void __launch_bounds__(128) flash_mma_kernel()
{
    extern __shared__ char sm[];
    uint32_t sb = smem_to_u32(sm);
    const int tid = threadIdx.x, wid = tid >> 5, lane = tid & 31;
    const int qt = blockIdx.x, h = blockIdx.y, b = blockIdx.z, g = h >> 2;
    const int q0 = qt * 64, wm = wid * 16;

    const __half* qsrc = g_qh + ((size_t)(b * T_ + q0)) * C_ + h * HD;
    const __half* ksrc = g_kh + (size_t)b * T_ * 512 + g * HD;
    const __half* vsrc = g_vh + (size_t)b * T_ * 512 + g * HD;

    // prologue: Q (group 0), KV0 (group 1), KV1 (group 2 if present)
    load_tile64(sb, qsrc, C_);
    CP_COMMIT();
    load_tile64(sb + 16384,         ksrc, 512);
    load_tile64(sb + 16384 + 16384, vsrc, 512);
    CP_COMMIT();
    if (qt >= 1) {
        uint32_t st = sb + 16384 + 32768;
        load_tile64(st,         ksrc + 64 * 512, 512);
        load_tile64(st + 16384, vsrc + 64 * 512, 512);
        CP_COMMIT();
    }
    if (qt >= 1) CP_WAIT2(); else CP_WAIT1();   // Q ready
    __syncthreads();

    // hoist Q fragments (16 rows x 128 cols per warp = 32 regs)
    uint32_t aqr[8][4];
    const int arow = wm + (lane & 15);
#pragma unroll
    for (int ks = 0; ks < 8; ks++)
        ldm4(aqr[ks], sb + (ks >> 2) * 8192 +
                      SWZ(arow * 128 + (ks & 3) * 32 + ((lane >> 4) & 1) * 16));

    float o[16][4];
#pragma unroll
    for (int i = 0; i < 16; i++)
#pragma unroll
        for (int c = 0; c < 4; c++) o[i][c] = 0.f;
    float l0 = 0.f, l1 = 0.f;

    int stage = 0;
    for (int kt = 0; kt <= qt; kt++) {
        if (kt + 1 <= qt) CP_WAIT1(); else CP_WAIT0();
        __syncthreads();
        if (kt + 2 <= qt) {
            int ps = stage + 2; if (ps >= 3) ps -= 3;
            uint32_t st = sb + 16384 + ps * 32768;
            size_t off = (size_t)(kt + 2) * 64 * 512;
            load_tile64(st,         ksrc + off, 512);
            load_tile64(st + 16384, vsrc + off, 512);
            CP_COMMIT();
        }

        uint32_t Kb = sb + 16384 + stage * 32768;
        uint32_t Vb = Kb + 16384;
        if (++stage == 3) stage = 0;

        // ---- S = Q K^T ----
        float sf[8][4];
#pragma unroll
        for (int f = 0; f < 8; f++)
#pragma unroll
            for (int c = 0; c < 4; c++) sf[f][c] = 0.f;

#pragma unroll
        for (int ks = 0; ks < 8; ks++) {
            const int brow_l = (lane & 7) + 8 * ((lane >> 4) & 1);
            const int bcol   = (ks & 3) * 32 + ((lane >> 3) & 1) * 16;
#pragma unroll
            for (int nf = 0; nf < 4; nf++) {
                uint32_t kb[4];
                ldm4(kb, Kb + (ks >> 2) * 8192 + SWZ((nf * 16 + brow_l) * 128 + bcol));
                mma_f16(sf[2 * nf],     aqr[ks], kb);
                mma_f16(sf[2 * nf + 1], aqr[ks], kb + 2);
            }
        }

        if (kt == qt) {
            const int r0 = wm + (lane >> 2);
            const int cb = (lane & 3) * 2;
#pragma unroll
            for (int f = 0; f < 8; f++)
#pragma unroll
                for (int c = 0; c < 4; c++) {
                    int col = f * 8 + cb + (c & 1);
                    int row = r0 + (c >> 1) * 8;
                    if (col > row) sf[f][c] = -1e30f;
                }
        }

        // ---- softmax numerator (fixed m=0; scores bounded) ----
#pragma unroll
        for (int f = 0; f < 8; f++) {
            sf[f][0] = __expf(sf[f][0]);
            sf[f][1] = __expf(sf[f][1]);
            sf[f][2] = __expf(sf[f][2]);
            sf[f][3] = __expf(sf[f][3]);
            l0 += sf[f][0] + sf[f][1];
            l1 += sf[f][2] + sf[f][3];
        }

        // ---- pack P ----
        uint32_t pa[4][4];
#pragma unroll
        for (int kp = 0; kp < 4; kp++) {
            const int f0 = 2 * kp, f1 = 2 * kp + 1;
#pragma unroll
            for (int half = 0; half < 2; half++) {
                pa[kp][half]     = pack_h2(sf[f0][2 * half], sf[f0][2 * half + 1]);
                pa[kp][2 + half] = pack_h2(sf[f1][2 * half], sf[f1][2 * half + 1]);
            }
        }

        // ---- O += P V ----
        const int krow = (lane & 7) + 8 * ((lane >> 3) & 1);
        const int nadd = 8 * (lane >> 4);
#pragma unroll
        for (int kp = 0; kp < 4; kp++) {
            const int kr = kp * 16 + krow;
#pragma unroll
            for (int nf = 0; nf < 8; nf++) {
                const int n0 = nf * 16;
                const uint32_t voff = ((uint32_t)(n0 >> 6)) * 8192 +
                                      SWZ(kr * 128 + ((n0 & 63) + nadd) * 2);
                uint32_t vb[4];
                ldm4t(vb, Vb + voff);
                mma_f16(o[2 * nf],     pa[kp], vb);
                mma_f16(o[2 * nf + 1], pa[kp], vb + 2);
            }
        }
    }

    // ---- final row-sum reduction (once) + normalize + store ----
    l0 += __shfl_xor_sync(0xffffffffu, l0, 1);
    l0 += __shfl_xor_sync(0xffffffffu, l0, 2);
    l1 += __shfl_xor_sync(0xffffffffu, l1, 1);
    l1 += __shfl_xor_sync(0xffffffffu, l1, 2);
    float inv0 = 1.f / l0, inv1 = 1.f / l1;
    size_t row0 = (size_t)(b * T_ + q0 + wm + (lane >> 2));
    int colb = h * HD + (lane & 3) * 2;
#pragma unroll
    for (int nf = 0; nf < 16; nf++) {
        int col = colb + nf * 8;
        *(uint32_t*)(g_yh + row0 * C_ + col) =
            pack_h2(o[nf][0] * inv0, o[nf][1] * inv0);
        *(uint32_t*)(g_yh + (row0 + 8) * C_ + col) =
            pack_h2(o[nf][2] * inv1, o[nf][3] * inv1);
    }
}

// ================= launch =================
extern "C" void kernel_launch(void* const* d_in, const int* in_sizes, int n_in,
                              void* d_out, int out_size)
{
    const float* x     = (const float*)d_in[0];
    const float* Wq    = (const float*)d_in[1];
    const float* Wkv   = (const float*)d_in[2];
    const float* Wproj = (const float*)d_in[3];
    float* out = (float*)d_out;

    float *qp, *kvp;
    __half *xh, *yh, *wqt, *wkvt, *wpt;
    cudaGetSymbolAddress((void**)&qp,   g_q);
    cudaGetSymbolAddress((void**)&kvp,  g_kv);
    cudaGetSymbolAddress((void**)&xh,   g_xh);
    cudaGetSymbolAddress((void**)&yh,   g_yh);
    cudaGetSymbolAddress((void**)&wqt,  g_wqt);
    cudaGetSymbolAddress((void**)&wkvt, g_wkvt);
    cudaGetSymbolAddress((void**)&wpt,  g_wpt);

    const int GEMM_SMEM  = 3 * 32768;           // 96 KB
    const int FLASH_SMEM = 16384 + 3 * 32768;   // 112 KB
    cudaFuncSetAttribute(gemm_mma, cudaFuncAttributeMaxDynamicSharedMemorySize, GEMM_SMEM);
    cudaFuncSetAttribute(flash_mma_kernel, cudaFuncAttributeMaxDynamicSharedMemorySize, FLASH_SMEM);

    // 1) stage inputs
    convert_h<<<2048, 512>>>((const float4*)x, (uint2*)xh, M_ * C_ / 4);
    transpose_h<<<dim3(C_ / 32, C_ / 32), dim3(32, 8)>>>(Wq, wqt, C_, C_);
    transpose_h<<<dim3(KVW / 32, C_ / 32), dim3(32, 8)>>>(Wkv, wkvt, C_, KVW);
    transpose_h<<<dim3(C_ / 32, C_ / 32), dim3(32, 8)>>>(Wproj, wpt, C_, C_);

    // 2) projections
    gemm_mma<<<dim3(C_ / 128, M_ / 128), 256, GEMM_SMEM>>>(xh, wqt, qp, C_, C_);
    gemm_mma<<<dim3(KVW / 128, M_ / 128), 256, GEMM_SMEM>>>(xh, wkvt, kvp, C_, KVW);

    // 3) l2norm + fp16 staging
    qnorm_h<<<M_, 256>>>();
    kvnorm_h<<<M_, 128>>>();

    // 4) flash attention -> yh
    flash_mma_kernel<<<dim3(T_ / 64, NH, B_), 128, FLASH_SMEM>>>();

    // 5) out = y @ Wproj
    gemm_mma<<<dim3(C_ / 128, M_ / 128), 256, GEMM_SMEM>>>(yh, wpt, out, C_, C_);
}

// round 9
// speedup vs baseline: 1.1135x; 1.1135x over previous
#include <cuda_runtime.h>
#include <cuda_fp16.h>
#include <math.h>
#include <stdint.h>

#define B_  4
#define T_  2048
#define C_  2048
#define NH  16
#define NKV 4
#define HD  128
#define KVW 1024
#define M_  (B_ * T_)   // 8192

// ---------------- scratch (no allocations allowed) ----------------
__device__ float g_q[(size_t)M_ * C_];          // x@Wq fp32
__device__ float g_kv[(size_t)M_ * KVW];        // x@Wkv fp32
__device__ __half g_xh[(size_t)M_ * C_];        // x fp16
__device__ __half g_qh[(size_t)M_ * C_];        // l2norm(q)*scale
__device__ __half g_kh[(size_t)M_ * 512];       // l2norm(k)
__device__ __half g_vh[(size_t)M_ * 512];       // v fp16
__device__ __half g_yh[(size_t)M_ * C_];        // attn out fp16
__device__ __half g_wqt[(size_t)C_ * C_];       // WqT  [N][K]
__device__ __half g_wkvt[(size_t)KVW * C_];     // WkvT [N][K]
__device__ __half g_wpt[(size_t)C_ * C_];       // WprojT [N][K]

// ================= helpers =================
__device__ __forceinline__ uint32_t smem_to_u32(const void* p) {
    uint32_t a;
    asm("{ .reg .u64 t; cvta.to.shared.u64 t, %1; cvt.u32.u64 %0, t; }"
        : "=r"(a) : "l"(p));
    return a;
}
#define SWZ(off) ((off) ^ (((off) >> 3) & 0x70))

__device__ __forceinline__ void ldm4(uint32_t* r, uint32_t addr) {
    asm volatile("ldmatrix.sync.aligned.m8n8.x4.shared.b16 {%0,%1,%2,%3}, [%4];"
        : "=r"(r[0]), "=r"(r[1]), "=r"(r[2]), "=r"(r[3]) : "r"(addr));
}
__device__ __forceinline__ void ldm2(uint32_t* r, uint32_t addr) {
    asm volatile("ldmatrix.sync.aligned.m8n8.x2.shared.b16 {%0,%1}, [%2];"
        : "=r"(r[0]), "=r"(r[1]) : "r"(addr));
}
__device__ __forceinline__ void ldm4t(uint32_t* r, uint32_t addr) {
    asm volatile("ldmatrix.sync.aligned.m8n8.x4.trans.shared.b16 {%0,%1,%2,%3}, [%4];"
        : "=r"(r[0]), "=r"(r[1]), "=r"(r[2]), "=r"(r[3]) : "r"(addr));
}
__device__ __forceinline__ void mma_f16(float* c, const uint32_t* a, const uint32_t* b) {
    asm volatile("mma.sync.aligned.m16n8k16.row.col.f32.f16.f16.f32 "
        "{%0,%1,%2,%3}, {%4,%5,%6,%7}, {%8,%9}, {%0,%1,%2,%3};"
        : "+f"(c[0]), "+f"(c[1]), "+f"(c[2]), "+f"(c[3])
        : "r"(a[0]), "r"(a[1]), "r"(a[2]), "r"(a[3]), "r"(b[0]), "r"(b[1]));
}
__device__ __forceinline__ void cp16(uint32_t dst, const void* src) {
    asm volatile("cp.async.cg.shared.global [%0], [%1], 16;" :: "r"(dst), "l"(src));
}
#define CP_COMMIT() asm volatile("cp.async.commit_group;" ::: "memory")
#define CP_WAIT0()  asm volatile("cp.async.wait_group 0;" ::: "memory")
#define CP_WAIT1()  asm volatile("cp.async.wait_group 1;" ::: "memory")
#define CP_WAIT2()  asm volatile("cp.async.wait_group 2;" ::: "memory")

__device__ __forceinline__ uint32_t pack_h2(float x, float y) {
    __half2 t = __float22half2_rn(make_float2(x, y));
    return *(uint32_t*)&t;
}

// ================= staging kernels =================
__global__ void __launch_bounds__(512) convert_h(const float4* __restrict__ x,
                                                 uint2* __restrict__ hi, int n4)
{
    for (int i = blockIdx.x * 512 + threadIdx.x; i < n4; i += gridDim.x * 512) {
        float4 v = x[i];
        hi[i] = make_uint2(pack_h2(v.x, v.y), pack_h2(v.z, v.w));
    }
}

// W [K][N] fp32 -> WT [N][K] fp16
__global__ void __launch_bounds__(256) transpose_h(const float* __restrict__ W,
                                                   __half* __restrict__ Tt, int K, int N)
{
    __shared__ float t[32][33];
    int n0 = blockIdx.x * 32, k0 = blockIdx.y * 32;
    int tx = threadIdx.x, ty = threadIdx.y;
#pragma unroll
    for (int j = 0; j < 4; j++)
        t[ty + 8 * j][tx] = W[(size_t)(k0 + ty + 8 * j) * N + n0 + tx];
    __syncthreads();
#pragma unroll
    for (int j = 0; j < 4; j++)
        Tt[(size_t)(n0 + ty + 8 * j) * K + k0 + tx] = __float2half_rn(t[tx][ty + 8 * j]);
}

// ================= HMMA fp16 GEMM, 2-stage (R7 proven: 64KB -> 3 CTA/SM) =================
__device__ __forceinline__ void cp_panel(uint32_t dstBase, const __half* __restrict__ src,
                                         int ldk, int row0, int k0)
{
    int tid = threadIdx.x;
#pragma unroll
    for (int i = 0; i < 4; i++) {
        int l = tid + 256 * i;
        int r = l >> 3, ch = l & 7;
        cp16(dstBase + SWZ(r * 128 + ch * 16), src + (size_t)(row0 + r) * ldk + k0 + ch * 8);
    }
}

__global__ void __launch_bounds__(256) gemm_mma(const __half* __restrict__ Ah,
                                                const __half* __restrict__ Bt,
                                                float* __restrict__ Cc, int K, int N)
{
    extern __shared__ char sm[];
    uint32_t sb = smem_to_u32(sm);
    const int tid = threadIdx.x, wid = tid >> 5, lane = tid & 31;
    const int row0 = blockIdx.y * 128, col0 = blockIdx.x * 128;
    const int wm = (wid >> 2) * 64;
    const int wn = (wid & 3) * 32;

    float acc[4][4][4];
#pragma unroll
    for (int a = 0; a < 4; a++)
#pragma unroll
        for (int b = 0; b < 4; b++)
#pragma unroll
            for (int c = 0; c < 4; c++) acc[a][b][c] = 0.f;

    const int KIT = K >> 6;
#pragma unroll
    for (int p = 0; p < 2; p++) {
        uint32_t st = sb + p * 32768;
        cp_panel(st,         Ah, K, row0, p * 64);
        cp_panel(st + 16384, Bt, K, col0, p * 64);
        CP_COMMIT();
    }

    for (int kc = 0; kc < KIT; kc++) {
        if (kc == KIT - 1) CP_WAIT0(); else CP_WAIT1();
        __syncthreads();

        uint32_t st = sb + (kc & 1) * 32768;
#pragma unroll
        for (int ks = 0; ks < 4; ks++) {
            uint32_t af[4][4], bf[4][2];
            const int arow = wm + (lane & 15);
            const int acol = ks * 32 + ((lane >> 4) & 1) * 16;
#pragma unroll
            for (int mt = 0; mt < 4; mt++)
                ldm4(af[mt], st + SWZ((uint32_t)(arow + mt * 16) * 128 + acol));
            const int brow = wn + (lane & 7);
            const int bcol = ks * 32 + ((lane >> 3) & 1) * 16;
#pragma unroll
            for (int nt = 0; nt < 4; nt++)
                ldm2(bf[nt], st + 16384 + SWZ((uint32_t)(brow + nt * 8) * 128 + bcol));
#pragma unroll
            for (int mt = 0; mt < 4; mt++)
#pragma unroll
                for (int nt = 0; nt < 4; nt++)
                    mma_f16(acc[mt][nt], af[mt], bf[nt]);
        }
        __syncthreads();

        if (kc + 2 < KIT) {
            uint32_t st2 = sb + (kc & 1) * 32768;
            int k0 = (kc + 2) * 64;
            cp_panel(st2,         Ah, K, row0, k0);
            cp_panel(st2 + 16384, Bt, K, col0, k0);
            CP_COMMIT();
        }
    }

    const int r0 = row0 + wm + (lane >> 2);
    const int c0 = col0 + wn + (lane & 3) * 2;
#pragma unroll
    for (int mt = 0; mt < 4; mt++)
#pragma unroll
        for (int nt = 0; nt < 4; nt++) {
            *(float2*)(Cc + (size_t)(r0 + mt * 16) * N + c0 + nt * 8) =
                make_float2(acc[mt][nt][0], acc[mt][nt][1]);
            *(float2*)(Cc + (size_t)(r0 + mt * 16 + 8) * N + c0 + nt * 8) =
                make_float2(acc[mt][nt][2], acc[mt][nt][3]);
        }
}

// ================= prepass: l2norm q -> fp16 (pre-scaled) =================
__global__ void __launch_bounds__(256) qnorm_h()
{
    const size_t row = blockIdx.x;
    const float4* p = (const float4*)(g_q + row * C_);
    float ss = 0.f;
    for (int i = threadIdx.x; i < C_ / 4; i += 256) {
        float4 v = p[i];
        ss += v.x * v.x + v.y * v.y + v.z * v.z + v.w * v.w;
    }
#pragma unroll
    for (int off = 16; off; off >>= 1) ss += __shfl_xor_sync(0xffffffffu, ss, off);
    __shared__ float red[8];
    if ((threadIdx.x & 31) == 0) red[threadIdx.x >> 5] = ss;
    __syncthreads();
    float tot = red[0] + red[1] + red[2] + red[3] + red[4] + red[5] + red[6] + red[7];
    float sc = 0.08838834764831845f / (sqrtf(tot) + 1e-12f);
    uint2* dst = (uint2*)(g_qh + row * C_);
    for (int i = threadIdx.x; i < C_ / 4; i += 256) {
        float4 v = p[i];
        dst[i] = make_uint2(pack_h2(v.x * sc, v.y * sc), pack_h2(v.z * sc, v.w * sc));
    }
}

// ================= prepass: l2norm k + v -> fp16 =================
__global__ void __launch_bounds__(128) kvnorm_h()
{
    const size_t row = blockIdx.x;
    const float4* kv = (const float4*)(g_kv + row * KVW);
    float4 kvv = kv[threadIdx.x];
    float ss = kvv.x * kvv.x + kvv.y * kvv.y + kvv.z * kvv.z + kvv.w * kvv.w;
#pragma unroll
    for (int off = 16; off; off >>= 1) ss += __shfl_xor_sync(0xffffffffu, ss, off);
    __shared__ float red[4];
    if ((threadIdx.x & 31) == 0) red[threadIdx.x >> 5] = ss;
    __syncthreads();
    float inv = 1.f / (sqrtf(red[0] + red[1] + red[2] + red[3]) + 1e-12f);

    ((uint2*)(g_kh + row * 512))[threadIdx.x] =
        make_uint2(pack_h2(kvv.x * inv, kvv.y * inv), pack_h2(kvv.z * inv, kvv.w * inv));

    float4 vv = kv[128 + threadIdx.x];
    ((uint2*)(g_vh + row * 512))[threadIdx.x] =
        make_uint2(pack_h2(vv.x, vv.y), pack_h2(vv.z, vv.w));
}

// ================= HMMA flash attention (R8 version: fixed-max, Q hoist, 3-stage) =================
__device__ __forceinline__ void load_tile64(uint32_t dstBase, const __half* __restrict__ src,
                                            size_t stride)
{
    int tid = threadIdx.x;
#pragma unroll
    for (int i = 0; i < 8; i++) {
        int lin = tid + 128 * i;
        int r = lin >> 4, ch = lin & 15;
        cp16(dstBase + (ch >> 3) * 8192 + SWZ(r * 128 + (ch & 7) * 16),
             src + (size_t)r * stride + ch * 8);
    }
}

__global__ void __launch_bounds__(128) flash_mma_kernel()
{
    extern __shared__ char sm[];
    uint32_t sb = smem_to_u32(sm);
    const int tid = threadIdx.x, wid = tid >> 5, lane = tid & 31;
    const int qt = blockIdx.x, h = blockIdx.y, b = blockIdx.z, g = h >> 2;
    const int q0 = qt * 64, wm = wid * 16;

    const __half* qsrc = g_qh + ((size_t)(b * T_ + q0)) * C_ + h * HD;
    const __half* ksrc = g_kh + (size_t)b * T_ * 512 + g * HD;
    const __half* vsrc = g_vh + (size_t)b * T_ * 512 + g * HD;

    load_tile64(sb, qsrc, C_);
    CP_COMMIT();
    load_tile64(sb + 16384,         ksrc, 512);
    load_tile64(sb + 16384 + 16384, vsrc, 512);
    CP_COMMIT();
    if (qt >= 1) {
        uint32_t st = sb + 16384 + 32768;
        load_tile64(st,         ksrc + 64 * 512, 512);
        load_tile64(st + 16384, vsrc + 64 * 512, 512);
        CP_COMMIT();
    }
    if (qt >= 1) CP_WAIT2(); else CP_WAIT1();
    __syncthreads();

    uint32_t aqr[8][4];
    const int arow = wm + (lane & 15);
#pragma unroll
    for (int ks = 0; ks < 8; ks++)
        ldm4(aqr[ks], sb + (ks >> 2) * 8192 +
                      SWZ(arow * 128 + (ks & 3) * 32 + ((lane >> 4) & 1) * 16));

    float o[16][4];
#pragma unroll
    for (int i = 0; i < 16; i++)
#pragma unroll
        for (int c = 0; c < 4; c++) o[i][c] = 0.f;
    float l0 = 0.f, l1 = 0.f;

    int stage = 0;
    for (int kt = 0; kt <= qt; kt++) {
        if (kt + 1 <= qt) CP_WAIT1(); else CP_WAIT0();
        __syncthreads();
        if (kt + 2 <= qt) {
            int ps = stage + 2; if (ps >= 3) ps -= 3;
            uint32_t st = sb + 16384 + ps * 32768;
            size_t off = (size_t)(kt + 2) * 64 * 512;
            load_tile64(st,         ksrc + off, 512);
            load_tile64(st + 16384, vsrc + off, 512);
            CP_COMMIT();
        }

        uint32_t Kb = sb + 16384 + stage * 32768;
        uint32_t Vb = Kb + 16384;
        if (++stage == 3) stage = 0;

        // ---- S = Q K^T ----
        float sf[8][4];
#pragma unroll
        for (int f = 0; f < 8; f++)
#pragma unroll
            for (int c = 0; c < 4; c++) sf[f][c] = 0.f;

#pragma unroll
        for (int ks = 0; ks < 8; ks++) {
            const int brow_l = (lane & 7) + 8 * ((lane >> 4) & 1);
            const int bcol   = (ks & 3) * 32 + ((lane >> 3) & 1) * 16;
#pragma unroll
            for (int nf = 0; nf < 4; nf++) {
                uint32_t kb[4];
                ldm4(kb, Kb + (ks >> 2) * 8192 + SWZ((nf * 16 + brow_l) * 128 + bcol));
                mma_f16(sf[2 * nf],     aqr[ks], kb);
                mma_f16(sf[2 * nf + 1], aqr[ks], kb + 2);
            }
        }

        if (kt == qt) {
            const int r0 = wm + (lane >> 2);
            const int cb = (lane & 3) * 2;
#pragma unroll
            for (int f = 0; f < 8; f++)
#pragma unroll
                for (int c = 0; c < 4; c++) {
                    int col = f * 8 + cb + (c & 1);
                    int row = r0 + (c >> 1) * 8;
                    if (col > row) sf[f][c] = -1e30f;
                }
        }

        // ---- softmax numerator (fixed m=0; scores bounded by l2-norms) ----
#pragma unroll
        for (int f = 0; f < 8; f++) {
            sf[f][0] = __expf(sf[f][0]);
            sf[f][1] = __expf(sf[f][1]);
            sf[f][2] = __expf(sf[f][2]);
            sf[f][3] = __expf(sf[f][3]);
            l0 += sf[f][0] + sf[f][1];
            l1 += sf[f][2] + sf[f][3];
        }

        // ---- pack P ----
        uint32_t pa[4][4];
#pragma unroll
        for (int kp = 0; kp < 4; kp++) {
            const int f0 = 2 * kp, f1 = 2 * kp + 1;
#pragma unroll
            for (int half = 0; half < 2; half++) {
                pa[kp][half]     = pack_h2(sf[f0][2 * half], sf[f0][2 * half + 1]);
                pa[kp][2 + half] = pack_h2(sf[f1][2 * half], sf[f1][2 * half + 1]);
            }
        }

        // ---- O += P V ----
        const int krow = (lane & 7) + 8 * ((lane >> 3) & 1);
        const int nadd = 8 * (lane >> 4);
#pragma unroll
        for (int kp = 0; kp < 4; kp++) {
            const int kr = kp * 16 + krow;
#pragma unroll
            for (int nf = 0; nf < 8; nf++) {
                const int n0 = nf * 16;
                const uint32_t voff = ((uint32_t)(n0 >> 6)) * 8192 +
                                      SWZ(kr * 128 + ((n0 & 63) + nadd) * 2);
                uint32_t vb[4];
                ldm4t(vb, Vb + voff);
                mma_f16(o[2 * nf],     pa[kp], vb);
                mma_f16(o[2 * nf + 1], pa[kp], vb + 2);
            }
        }
    }

    // ---- final row-sum reduction + normalize + store ----
    l0 += __shfl_xor_sync(0xffffffffu, l0, 1);
    l0 += __shfl_xor_sync(0xffffffffu, l0, 2);
    l1 += __shfl_xor_sync(0xffffffffu, l1, 1);
    l1 += __shfl_xor_sync(0xffffffffu, l1, 2);
    float inv0 = 1.f / l0, inv1 = 1.f / l1;
    size_t row0 = (size_t)(b * T_ + q0 + wm + (lane >> 2));
    int colb = h * HD + (lane & 3) * 2;
#pragma unroll
    for (int nf = 0; nf < 16; nf++) {
        int col = colb + nf * 8;
        *(uint32_t*)(g_yh + row0 * C_ + col) =
            pack_h2(o[nf][0] * inv0, o[nf][1] * inv0);
        *(uint32_t*)(g_yh + (row0 + 8) * C_ + col) =
            pack_h2(o[nf][2] * inv1, o[nf][3] * inv1);
    }
}

// ================= launch =================
extern "C" void kernel_launch(void* const* d_in, const int* in_sizes, int n_in,
                              void* d_out, int out_size)
{
    const float* x     = (const float*)d_in[0];
    const float* Wq    = (const float*)d_in[1];
    const float* Wkv   = (const float*)d_in[2];
    const float* Wproj = (const float*)d_in[3];
    float* out = (float*)d_out;

    float *qp, *kvp;
    __half *xh, *yh, *wqt, *wkvt, *wpt;
    cudaGetSymbolAddress((void**)&qp,   g_q);
    cudaGetSymbolAddress((void**)&kvp,  g_kv);
    cudaGetSymbolAddress((void**)&xh,   g_xh);
    cudaGetSymbolAddress((void**)&yh,   g_yh);
    cudaGetSymbolAddress((void**)&wqt,  g_wqt);
    cudaGetSymbolAddress((void**)&wkvt, g_wkvt);
    cudaGetSymbolAddress((void**)&wpt,  g_wpt);

    const int GEMM_SMEM  = 2 * 32768;           // 64 KB -> 3 CTA/SM
    const int FLASH_SMEM = 16384 + 3 * 32768;   // 112 KB -> 2 CTA/SM
    cudaFuncSetAttribute(gemm_mma, cudaFuncAttributeMaxDynamicSharedMemorySize, GEMM_SMEM);
    cudaFuncSetAttribute(flash_mma_kernel, cudaFuncAttributeMaxDynamicSharedMemorySize, FLASH_SMEM);

    // 1) stage inputs
    convert_h<<<2048, 512>>>((const float4*)x, (uint2*)xh, M_ * C_ / 4);
    transpose_h<<<dim3(C_ / 32, C_ / 32), dim3(32, 8)>>>(Wq, wqt, C_, C_);
    transpose_h<<<dim3(KVW / 32, C_ / 32), dim3(32, 8)>>>(Wkv, wkvt, C_, KVW);
    transpose_h<<<dim3(C_ / 32, C_ / 32), dim3(32, 8)>>>(Wproj, wpt, C_, C_);

    // 2) projections
    gemm_mma<<<dim3(C_ / 128, M_ / 128), 256, GEMM_SMEM>>>(xh, wqt, qp, C_, C_);
    gemm_mma<<<dim3(KVW / 128, M_ / 128), 256, GEMM_SMEM>>>(xh, wkvt, kvp, C_, KVW);

    // 3) l2norm + fp16 staging
    qnorm_h<<<M_, 256>>>();
    kvnorm_h<<<M_, 128>>>();

    // 4) flash attention -> yh
    flash_mma_kernel<<<dim3(T_ / 64, NH, B_), 128, FLASH_SMEM>>>();

    // 5) out = y @ Wproj
    gemm_mma<<<dim3(C_ / 128, M_ / 128), 256, GEMM_SMEM>>>(yh, wpt, out, C_, C_);
}